// round 5
// baseline (speedup 1.0000x reference)
#include <cuda_runtime.h>
#include <cuda_bf16.h>

// wACSFRad R5: bucket payload = (rij, s) computed in scatter.
//  pack:    xyzw[i]=(x,y,z,float(z_i)); cursor[i]=0
//  scatter: per edge: gather both endpoints, rij=|xi-xj|, s=fc(rij)*w;
//           bucket[recv*CAP + atomicAdd(cursor)] = (rij, s)
//  compute: 4 lanes/node; lanes read bucket sequentially (same address in
//           group -> L1 broadcast), each lane owns params k=r,r+4,... fully
//           register-resident. Pure FMA+MUFU inner loop, plain store.
//
// Inputs: z i32[100000], xyz f32[100000,3], eij i32[3200000,2], eta_mu f32[118,22,2]
// Output: f32 [100000,22]

#define N_NODES_MAX 100000
#define N_TYPES 118
#define N_PARAMS 22
#define CAP 128
#define PI_OVER_CUT 0.39269908169872414f

__device__ float4 g_xyzw[N_NODES_MAX];
__device__ int    g_cursor[N_NODES_MAX];
__device__ float2 g_bucket[(long long)N_NODES_MAX * CAP];   // (rij, s)

__global__ void pack_nodes_kernel(const int* __restrict__ z,
                                  const float* __restrict__ xyz, int n) {
    int i = blockIdx.x * blockDim.x + threadIdx.x;
    if (i < n) {
        float4 v;
        v.x = xyz[3 * i + 0];
        v.y = xyz[3 * i + 1];
        v.z = xyz[3 * i + 2];
        v.w = (float)z[i];          // exact for 0..117; weight AND type
        g_xyzw[i] = v;
        g_cursor[i] = 0;
    }
}

__device__ __forceinline__ void scatter_one(int recv, int send,
                                            const float2* __restrict__ eta_mu2,
                                            float* __restrict__ out) {
    const float4 a = __ldg(&g_xyzw[recv]);
    const float4 b = __ldg(&g_xyzw[send]);
    const float dx = a.x - b.x, dy = a.y - b.y, dz = a.z - b.z;
    const float rij = sqrtf(fmaf(dx, dx, fmaf(dy, dy, dz * dz)));
    const float s = 0.5f * (__cosf(fminf(rij, 8.0f) * PI_OVER_CUT) + 1.0f) * b.w;

    const int pos = atomicAdd(&g_cursor[recv], 1);
    if (pos < CAP) {
        g_bucket[(long long)recv * CAP + pos] = make_float2(rij, s);
    } else {
        // overflow fallback (never taken for Poisson(32) degrees)
        const int t = (int)a.w;
        float* o = out + (long long)recv * N_PARAMS;
        for (int k = 0; k < N_PARAMS; k++) {
            const float2 p = __ldg(&eta_mu2[t * N_PARAMS + k]);
            const float d = rij - p.y;
            atomicAdd(o + k, s * __expf(-p.x * d * d));
        }
    }
}

__global__ void __launch_bounds__(256) scatter_kernel(
    const int4* __restrict__ eij2,        // 2 edges per int4
    const int2* __restrict__ eij,
    const float2* __restrict__ eta_mu2,
    float* __restrict__ out,
    int n_pairs, int n_edges)
{
    const int i = blockIdx.x * blockDim.x + threadIdx.x;
    if (i < n_pairs) {
        const int4 v = __ldg(&eij2[i]);
        scatter_one(v.x, v.y, eta_mu2, out);
        scatter_one(v.z, v.w, eta_mu2, out);
    }
    if (i == 0 && (n_edges & 1)) {
        const int2 t = __ldg(&eij[n_edges - 1]);
        scatter_one(t.x, t.y, eta_mu2, out);
    }
}

__global__ void __launch_bounds__(256) compute_kernel(
    const float2* __restrict__ eta_mu2,
    float* __restrict__ out,
    int n_nodes)
{
    // stage table in shared: 118*22 float2 = 20768 B
    __shared__ float2 tbl[N_TYPES * N_PARAMS];
    for (int i = threadIdx.x; i < N_TYPES * N_PARAMS; i += blockDim.x)
        tbl[i] = eta_mu2[i];
    __syncthreads();

    const int gid = blockIdx.x * blockDim.x + threadIdx.x;
    int node = gid >> 2;
    const int r = gid & 3;
    if (node >= n_nodes) node = n_nodes - 1;       // benign duplicate work

    const float4 a = __ldg(&g_xyzw[node]);
    const int t = (int)a.w;
    const int deg_raw = g_cursor[node];
    const int deg = deg_raw < CAP ? deg_raw : CAP;
    const float2* __restrict__ bkt = g_bucket + (long long)node * CAP;

    // lane r owns params k = r, r+4, ... (6 slots; last 2 of lanes 2,3 unused)
    float eta[6], mu[6];
    #pragma unroll
    for (int j = 0; j < 6; j++) {
        const int k = r + 4 * j;
        const int kk = k < N_PARAMS ? k : (N_PARAMS - 1);
        const float2 p = tbl[t * N_PARAMS + kk];
        eta[j] = p.x; mu[j] = p.y;
    }
    float acc[6] = {0.f, 0.f, 0.f, 0.f, 0.f, 0.f};

    // All 4 lanes in the group read the SAME address -> L1 broadcast.
    // Pure FMA/MUFU body; unroll 2 for scheduling.
    #pragma unroll 2
    for (int e = 0; e < deg; e++) {
        const float2 rs = __ldg(&bkt[e]);
        #pragma unroll
        for (int q = 0; q < 6; q++) {
            const float d = rs.x - mu[q];
            acc[q] = fmaf(rs.y, __expf(-eta[q] * d * d), acc[q]);
        }
    }

    float* o = out + (long long)node * N_PARAMS;
    if (deg_raw <= CAP) {
        #pragma unroll
        for (int j = 0; j < 6; j++) {
            const int k = r + 4 * j;
            if (k < N_PARAMS) o[k] = acc[j];
        }
    } else {
        #pragma unroll
        for (int j = 0; j < 6; j++) {
            const int k = r + 4 * j;
            if (k < N_PARAMS) atomicAdd(o + k, acc[j]);
        }
    }
}

extern "C" void kernel_launch(void* const* d_in, const int* in_sizes, int n_in,
                              void* d_out, int out_size) {
    const int*    z       = (const int*)   d_in[0];
    const float*  xyz     = (const float*) d_in[1];
    const int2*   eij     = (const int2*)  d_in[2];
    const int4*   eij2    = (const int4*)  d_in[2];
    const float2* eta_mu2 = (const float2*)d_in[3];
    float*        out     = (float*)d_out;

    const int n_nodes = in_sizes[0];
    const int n_edges = in_sizes[2] / 2;
    const int n_pairs = n_edges / 2;

    cudaMemsetAsync(d_out, 0, (size_t)out_size * sizeof(float), 0);

    pack_nodes_kernel<<<(n_nodes + 255) / 256, 256>>>(z, xyz, n_nodes);
    scatter_kernel<<<(n_pairs + 255) / 256, 256>>>(eij2, eij, eta_mu2, out,
                                                   n_pairs, n_edges);

    const int threads_needed = n_nodes * 4;
    compute_kernel<<<(threads_needed + 255) / 256, 256>>>(eta_mu2, out, n_nodes);
}

// round 6
// speedup vs baseline: 1.4064x; 1.4064x over previous
#include <cuda_runtime.h>
#include <cuda_bf16.h>

// wACSFRad R6: bucket-CSR with DEAD-EDGE CULLING.
//  fc(rij) = 0.5*(cos(min(rij,8)*pi/8)+1) == 0 for rij >= 8  -> ~57% of edges
//  contribute exactly nothing (s = fc*w = 0). Scatter computes (rij,s) and
//  stores ONLY s != 0 edges into the per-recv bucket. Compute is pure math on
//  the ~43% survivors, atomic-free coalesced output.
//
// Inputs: z i32[100000], xyz f32[100000,3], eij i32[3200000,2], eta_mu f32[118,22,2]
// Output: f32 [100000,22]

#define N_NODES_MAX 100000
#define N_TYPES 118
#define N_PARAMS 22
#define CAP 64                  // effective degree ~Binom(32,0.43), max≈40
#define PI_OVER_CUT 0.39269908169872414f

__device__ float4 g_xyzw[N_NODES_MAX];
__device__ int    g_cursor[N_NODES_MAX];
__device__ float2 g_bucket[(long long)N_NODES_MAX * CAP];   // (rij, s)

__global__ void pack_nodes_kernel(const int* __restrict__ z,
                                  const float* __restrict__ xyz, int n) {
    int i = blockIdx.x * blockDim.x + threadIdx.x;
    if (i < n) {
        float4 v;
        v.x = xyz[3 * i + 0];
        v.y = xyz[3 * i + 1];
        v.z = xyz[3 * i + 2];
        v.w = (float)z[i];          // exact for 0..117; weight AND type
        g_xyzw[i] = v;
        g_cursor[i] = 0;
    }
}

__device__ __forceinline__ void scatter_one(int recv, int send,
                                            const float2* __restrict__ eta_mu2,
                                            float* __restrict__ out) {
    const float4 a = __ldg(&g_xyzw[recv]);
    const float4 b = __ldg(&g_xyzw[send]);
    const float dx = a.x - b.x, dy = a.y - b.y, dz = a.z - b.z;
    const float rij = sqrtf(fmaf(dx, dx, fmaf(dy, dy, dz * dz)));

    // cull: fc == 0 for rij >= 8 (cos(pi) = -1), and w may be 0 (type 0)
    if (rij >= 8.0f) return;
    const float s = 0.5f * (__cosf(rij * PI_OVER_CUT) + 1.0f) * b.w;
    if (s == 0.0f) return;

    const int pos = atomicAdd(&g_cursor[recv], 1);
    if (pos < CAP) {
        g_bucket[(long long)recv * CAP + pos] = make_float2(rij, s);
    } else {
        // overflow fallback (never taken at these degrees, but correct)
        const int t = (int)a.w;
        float* o = out + (long long)recv * N_PARAMS;
        for (int k = 0; k < N_PARAMS; k++) {
            const float2 p = __ldg(&eta_mu2[t * N_PARAMS + k]);
            const float d = rij - p.y;
            atomicAdd(o + k, s * __expf(-p.x * d * d));
        }
    }
}

__global__ void __launch_bounds__(256) scatter_kernel(
    const int4* __restrict__ eij2,        // 2 edges per int4
    const int2* __restrict__ eij,
    const float2* __restrict__ eta_mu2,
    float* __restrict__ out,
    int n_pairs, int n_edges)
{
    const int i = blockIdx.x * blockDim.x + threadIdx.x;
    if (i < n_pairs) {
        const int4 v = __ldg(&eij2[i]);
        scatter_one(v.x, v.y, eta_mu2, out);
        scatter_one(v.z, v.w, eta_mu2, out);
    }
    if (i == 0 && (n_edges & 1)) {
        const int2 t = __ldg(&eij[n_edges - 1]);
        scatter_one(t.x, t.y, eta_mu2, out);
    }
}

__global__ void __launch_bounds__(256) compute_kernel(
    const float2* __restrict__ eta_mu2,
    float* __restrict__ out,
    int n_nodes)
{
    // stage table in shared: 118*22 float2 = 20768 B
    __shared__ float2 tbl[N_TYPES * N_PARAMS];
    for (int i = threadIdx.x; i < N_TYPES * N_PARAMS; i += blockDim.x)
        tbl[i] = eta_mu2[i];
    __syncthreads();

    const int gid = blockIdx.x * blockDim.x + threadIdx.x;
    int node = gid >> 2;
    const int r = gid & 3;
    if (node >= n_nodes) node = n_nodes - 1;       // benign duplicate work

    const float4 a = __ldg(&g_xyzw[node]);
    const int t = (int)a.w;
    const int deg_raw = g_cursor[node];
    const int deg = deg_raw < CAP ? deg_raw : CAP;
    const float2* __restrict__ bkt = g_bucket + (long long)node * CAP;

    // lane r owns params k = r, r+4, ... (6 slots; last 2 of lanes 2,3 unused)
    float eta[6], mu[6];
    #pragma unroll
    for (int j = 0; j < 6; j++) {
        const int k = r + 4 * j;
        const int kk = k < N_PARAMS ? k : (N_PARAMS - 1);
        const float2 p = tbl[t * N_PARAMS + kk];
        eta[j] = p.x; mu[j] = p.y;
    }
    float acc[6] = {0.f, 0.f, 0.f, 0.f, 0.f, 0.f};

    // All 4 lanes in the group read the SAME address -> L1 broadcast.
    #pragma unroll 2
    for (int e = 0; e < deg; e++) {
        const float2 rs = __ldg(&bkt[e]);
        #pragma unroll
        for (int q = 0; q < 6; q++) {
            const float d = rs.x - mu[q];
            acc[q] = fmaf(rs.y, __expf(-eta[q] * d * d), acc[q]);
        }
    }

    float* o = out + (long long)node * N_PARAMS;
    if (deg_raw <= CAP) {
        #pragma unroll
        for (int j = 0; j < 6; j++) {
            const int k = r + 4 * j;
            if (k < N_PARAMS) o[k] = acc[j];
        }
    } else {
        #pragma unroll
        for (int j = 0; j < 6; j++) {
            const int k = r + 4 * j;
            if (k < N_PARAMS) atomicAdd(o + k, acc[j]);
        }
    }
}

extern "C" void kernel_launch(void* const* d_in, const int* in_sizes, int n_in,
                              void* d_out, int out_size) {
    const int*    z       = (const int*)   d_in[0];
    const float*  xyz     = (const float*) d_in[1];
    const int2*   eij     = (const int2*)  d_in[2];
    const int4*   eij2    = (const int4*)  d_in[2];
    const float2* eta_mu2 = (const float2*)d_in[3];
    float*        out     = (float*)d_out;

    const int n_nodes = in_sizes[0];
    const int n_edges = in_sizes[2] / 2;
    const int n_pairs = n_edges / 2;

    cudaMemsetAsync(d_out, 0, (size_t)out_size * sizeof(float), 0);

    pack_nodes_kernel<<<(n_nodes + 255) / 256, 256>>>(z, xyz, n_nodes);
    scatter_kernel<<<(n_pairs + 255) / 256, 256>>>(eij2, eij, eta_mu2, out,
                                                   n_pairs, n_edges);

    const int threads_needed = n_nodes * 4;
    compute_kernel<<<(threads_needed + 255) / 256, 256>>>(eta_mu2, out, n_nodes);
}